// round 1
// baseline (speedup 1.0000x reference)
#include <cuda_runtime.h>
#include <math.h>

// ---------------- scratch (device globals; no allocation allowed) ----------
__device__ float g_scores[512];        // attn logits
__device__ float g_aw[512];            // attn softmax weights
__device__ float g_ctx[2048];          // attn_applied
__device__ float g_x[2048];            // relu(attn_combine)
__device__ float g_gates[12288];       // gi[0:6144), gh[6144:12288)
__device__ float g_hnew[2048];         // new hidden
__device__ float g_lse[1];             // logsumexp of raw logits

#define H 2048
#define V 50257
#define L 512

// ---------------- reductions ----------------
__device__ __forceinline__ float warpSum(float v) {
#pragma unroll
    for (int o = 16; o; o >>= 1) v += __shfl_down_sync(0xffffffffu, v, o);
    return v;
}
__device__ __forceinline__ float blockSum256(float v) {
    __shared__ float s[8];
    int lane = threadIdx.x & 31, w = threadIdx.x >> 5;
    v = warpSum(v);
    if (lane == 0) s[w] = v;
    __syncthreads();
    if (w == 0) {
        v = (lane < 8) ? s[lane] : 0.f;
        v = warpSum(v);
        if (lane == 0) s[0] = v;
    }
    __syncthreads();
    return s[0];
}

// K1: attn scores[l] = attn_W[l,:] . cat(emb, h) + attn_b[l]
__global__ void k_attn_scores(const int* token, const float* hidden,
                              const float* embedding, const float* attn_W,
                              const float* attn_b) {
    int row = blockIdx.x;
    const float4* w4 = (const float4*)(attn_W + (size_t)row * 2 * H);
    const float4* emb4 = (const float4*)(embedding + (size_t)token[0] * H);
    const float4* hid4 = (const float4*)hidden;
    float acc = 0.f;
    for (int i = threadIdx.x; i < 2 * H / 4; i += blockDim.x) {
        float4 w = w4[i];
        float4 v = (i < H / 4) ? __ldg(&emb4[i]) : __ldg(&hid4[i - H / 4]);
        acc += w.x * v.x + w.y * v.y + w.z * v.z + w.w * v.w;
    }
    acc = blockSum256(acc);
    if (threadIdx.x == 0) g_scores[row] = acc + attn_b[row];
}

// K2: softmax over 512 scores (single block, 512 threads); also writes attn
// weights to the output buffer.
__global__ void k_softmax(float* out_aw) {
    __shared__ float s[32];
    int tid = threadIdx.x, lane = tid & 31, w = tid >> 5;
    float v = g_scores[tid];
    // block max
    float m = v;
#pragma unroll
    for (int o = 16; o; o >>= 1) m = fmaxf(m, __shfl_down_sync(0xffffffffu, m, o));
    if (lane == 0) s[w] = m;
    __syncthreads();
    if (w == 0) {
        m = (lane < 16) ? s[lane] : -1e30f;
#pragma unroll
        for (int o = 16; o; o >>= 1) m = fmaxf(m, __shfl_down_sync(0xffffffffu, m, o));
        if (lane == 0) s[0] = m;
    }
    __syncthreads();
    m = s[0];
    __syncthreads();
    float e = expf(v - m);
    float sum = e;
#pragma unroll
    for (int o = 16; o; o >>= 1) sum += __shfl_down_sync(0xffffffffu, sum, o);
    if (lane == 0) s[w] = sum;
    __syncthreads();
    if (w == 0) {
        sum = (lane < 16) ? s[lane] : 0.f;
        sum = warpSum(sum);
        if (lane == 0) s[1] = sum;
    }
    __syncthreads();
    float aw = e / s[1];
    g_aw[tid] = aw;
    out_aw[tid] = aw;
}

// K3: ctx[col] = sum_l aw[l] * enc[l, col]   (8 blocks x 256 threads)
__global__ void k_context(const float* enc) {
    __shared__ float s_aw[L];
    for (int i = threadIdx.x; i < L; i += blockDim.x) s_aw[i] = g_aw[i];
    __syncthreads();
    int col = blockIdx.x * blockDim.x + threadIdx.x;
    float acc = 0.f;
#pragma unroll 8
    for (int l = 0; l < L; l++) acc += s_aw[l] * __ldg(&enc[(size_t)l * H + col]);
    g_ctx[col] = acc;
}

// K4: x[i] = relu(comb_W[i,:] . cat(emb, ctx) + comb_b[i])
__global__ void k_combine(const int* token, const float* embedding,
                          const float* comb_W, const float* comb_b) {
    int row = blockIdx.x;
    const float4* w4 = (const float4*)(comb_W + (size_t)row * 2 * H);
    const float4* emb4 = (const float4*)(embedding + (size_t)token[0] * H);
    const float4* ctx4 = (const float4*)g_ctx;
    float acc = 0.f;
    for (int i = threadIdx.x; i < 2 * H / 4; i += blockDim.x) {
        float4 w = w4[i];
        float4 v = (i < H / 4) ? __ldg(&emb4[i]) : __ldg(&ctx4[i - H / 4]);
        acc += w.x * v.x + w.y * v.y + w.z * v.z + w.w * v.w;
    }
    acc = blockSum256(acc);
    if (threadIdx.x == 0) g_x[row] = fmaxf(acc + comb_b[row], 0.f);
}

// K5: gi = w_ih @ x + b_ih ; gh = w_hh @ h + b_hh  (12288 blocks)
__global__ void k_gates(const float* w_ih, const float* w_hh,
                        const float* b_ih, const float* b_hh,
                        const float* hidden) {
    int row = blockIdx.x;
    const float4* w4;
    const float4* v4;
    float bias;
    if (row < 3 * H) {
        w4 = (const float4*)(w_ih + (size_t)row * H);
        v4 = (const float4*)g_x;
        bias = b_ih[row];
    } else {
        w4 = (const float4*)(w_hh + (size_t)(row - 3 * H) * H);
        v4 = (const float4*)hidden;
        bias = b_hh[row - 3 * H];
    }
    float acc = 0.f;
    for (int i = threadIdx.x; i < H / 4; i += blockDim.x) {
        float4 w = w4[i];
        float4 v = __ldg(&v4[i]);
        acc += w.x * v.x + w.y * v.y + w.z * v.z + w.w * v.w;
    }
    acc = blockSum256(acc);
    if (threadIdx.x == 0) g_gates[row] = acc + bias;
}

// K6: GRU gate combine -> h_new (also written to output)
__global__ void k_hnew(const float* hidden, float* out_h) {
    int i = blockIdx.x * blockDim.x + threadIdx.x;
    if (i >= H) return;
    const float* gi = g_gates;
    const float* gh = g_gates + 3 * H;
    float r = 1.f / (1.f + expf(-(gi[i] + gh[i])));
    float z = 1.f / (1.f + expf(-(gi[H + i] + gh[H + i])));
    float n = tanhf(gi[2 * H + i] + r * gh[2 * H + i]);
    float hn = (1.f - z) * n + z * hidden[i];
    g_hnew[i] = hn;
    out_h[i] = hn;
}

// K7: raw logits[v] = out_W[v,:] . h_new + out_b[v]   (THE big GEMV, 412 MB)
__global__ void k_logits(const float* out_W, const float* out_b, float* out) {
    int row = blockIdx.x;
    const float4* w4 = (const float4*)(out_W + (size_t)row * H);
    const float4* v4 = (const float4*)g_hnew;
    float acc = 0.f;
#pragma unroll 2
    for (int i = threadIdx.x; i < H / 4; i += blockDim.x) {
        float4 w = __ldg(&w4[i]);
        float4 v = __ldg(&v4[i]);
        acc += w.x * v.x + w.y * v.y + w.z * v.z + w.w * v.w;
    }
    acc = blockSum256(acc);
    if (threadIdx.x == 0) out[row] = acc + out_b[row];
}

// K8: logsumexp over raw logits (single block, 1024 threads)
__global__ void k_lse(const float* out) {
    __shared__ float s[32];
    int tid = threadIdx.x, lane = tid & 31, w = tid >> 5;
    float m = -1e30f;
    for (int i = tid; i < V; i += 1024) m = fmaxf(m, out[i]);
#pragma unroll
    for (int o = 16; o; o >>= 1) m = fmaxf(m, __shfl_down_sync(0xffffffffu, m, o));
    if (lane == 0) s[w] = m;
    __syncthreads();
    if (w == 0) {
        m = s[lane];
#pragma unroll
        for (int o = 16; o; o >>= 1) m = fmaxf(m, __shfl_down_sync(0xffffffffu, m, o));
        if (lane == 0) s[0] = m;
    }
    __syncthreads();
    m = s[0];
    float sum = 0.f;
    for (int i = tid; i < V; i += 1024) sum += expf(out[i] - m);
    sum = warpSum(sum);
    __syncthreads();
    if (lane == 0) s[w] = sum;
    __syncthreads();
    if (w == 0) {
        sum = s[lane];
        sum = warpSum(sum);
        if (lane == 0) g_lse[0] = m + logf(sum);
    }
}

// K9: out[v] -= lse
__global__ void k_logsoftmax(float* out) {
    int i = blockIdx.x * blockDim.x + threadIdx.x;
    if (i < V) out[i] -= g_lse[0];
}

extern "C" void kernel_launch(void* const* d_in, const int* in_sizes, int n_in,
                              void* d_out, int out_size) {
    const int*   token     = (const int*)d_in[0];
    const float* hidden    = (const float*)d_in[1];
    const float* enc       = (const float*)d_in[2];
    const float* embedding = (const float*)d_in[3];
    const float* attn_W    = (const float*)d_in[4];
    const float* attn_b    = (const float*)d_in[5];
    const float* comb_W    = (const float*)d_in[6];
    const float* comb_b    = (const float*)d_in[7];
    const float* w_ih      = (const float*)d_in[8];
    const float* w_hh      = (const float*)d_in[9];
    const float* b_ih      = (const float*)d_in[10];
    const float* b_hh      = (const float*)d_in[11];
    const float* out_W     = (const float*)d_in[12];
    const float* out_b     = (const float*)d_in[13];

    float* out = (float*)d_out;
    // Output layout (reference return order): logits[V], h_new[H], attn_weights[L]
    float* out_logits = out;
    float* out_h      = out + V;
    float* out_aw     = out + V + H;

    k_attn_scores<<<L, 256>>>(token, hidden, embedding, attn_W, attn_b);
    k_softmax<<<1, L>>>(out_aw);
    k_context<<<H / 256, 256>>>(enc);
    k_combine<<<H, 256>>>(token, embedding, comb_W, comb_b);
    k_gates<<<6 * H, 256>>>(w_ih, w_hh, b_ih, b_hh, hidden);
    k_hnew<<<H / 256, 256>>>(hidden, out_h);
    k_logits<<<V, 256>>>(out_W, out_b, out_logits);
    k_lse<<<1, 1024>>>(out_logits);
    k_logsoftmax<<<(V + 255) / 256, 256>>>(out_logits);
}

// round 2
// speedup vs baseline: 1.3239x; 1.3239x over previous
#include <cuda_runtime.h>
#include <math.h>

// ---------------- scratch (device globals; no allocation allowed) ----------
__device__ float g_scores[512];        // attn logits
__device__ float g_aw[512];            // attn softmax weights
__device__ float g_ctx[2048];          // attn_applied
__device__ float g_x[2048];            // relu(attn_combine)
__device__ float g_gates[12288];       // gi[0:6144), gh[6144:12288)
__device__ float g_hnew[2048];         // new hidden
__device__ float g_lse[1];             // logsumexp of raw logits

#define H 2048
#define V 50257
#define L 512

__device__ __forceinline__ float warpSum(float v) {
#pragma unroll
    for (int o = 16; o; o >>= 1) v += __shfl_down_sync(0xffffffffu, v, o);
    return v;
}

// ---------------------------------------------------------------------------
// K1: attn scores[l] = attn_W[l,:] . cat(emb, h) + attn_b[l]
// warp-per-row; row length 2H=4096 floats = 1024 float4 -> 32 per lane.
__global__ void k_attn_scores(const int* __restrict__ token,
                              const float* __restrict__ hidden,
                              const float* __restrict__ embedding,
                              const float* __restrict__ attn_W,
                              const float* __restrict__ attn_b) {
    int warp = (blockIdx.x * blockDim.x + threadIdx.x) >> 5;
    int lane = threadIdx.x & 31;
    if (warp >= L) return;
    const float4* w4   = (const float4*)(attn_W + (size_t)warp * 2 * H);
    const float4* emb4 = (const float4*)(embedding + (size_t)__ldg(token) * H);
    const float4* hid4 = (const float4*)hidden;
    float acc[4] = {0.f, 0.f, 0.f, 0.f};
#pragma unroll
    for (int j = 0; j < 16; j++) {          // first half: emb
        int i = lane + 32 * j;
        float4 w = w4[i];
        float4 x = __ldg(&emb4[i]);
        acc[j & 3] += w.x * x.x + w.y * x.y + w.z * x.z + w.w * x.w;
    }
#pragma unroll
    for (int j = 0; j < 16; j++) {          // second half: hidden
        int i = lane + 32 * j;
        float4 w = w4[i + 512];
        float4 x = __ldg(&hid4[i]);
        acc[j & 3] += w.x * x.x + w.y * x.y + w.z * x.z + w.w * x.w;
    }
    float a = warpSum(acc[0] + acc[1] + acc[2] + acc[3]);
    if (lane == 0) g_scores[warp] = a + __ldg(&attn_b[warp]);
}

// ---------------------------------------------------------------------------
// K2: softmax over 512 scores (1 block, 512 threads); writes attn weights to
// output; also zeroes g_ctx for K3.
__global__ void k_softmax(float* __restrict__ out_aw) {
    __shared__ float s[32];
    int tid = threadIdx.x, lane = tid & 31, w = tid >> 5;
    // zero ctx (4 per thread)
    ((float4*)g_ctx)[tid] = make_float4(0.f, 0.f, 0.f, 0.f);
    float v = g_scores[tid];
    float m = v;
#pragma unroll
    for (int o = 16; o; o >>= 1) m = fmaxf(m, __shfl_down_sync(0xffffffffu, m, o));
    if (lane == 0) s[w] = m;
    __syncthreads();
    if (w == 0) {
        m = (lane < 16) ? s[lane] : -1e30f;
#pragma unroll
        for (int o = 16; o; o >>= 1) m = fmaxf(m, __shfl_down_sync(0xffffffffu, m, o));
        if (lane == 0) s[0] = m;
    }
    __syncthreads();
    m = s[0];
    __syncthreads();
    float e = expf(v - m);
    float sum = warpSum(e);
    if (lane == 0) s[w] = sum;
    __syncthreads();
    if (w == 0) {
        sum = (lane < 16) ? s[lane] : 0.f;
        sum = warpSum(sum);
        if (lane == 0) s[1] = sum;
    }
    __syncthreads();
    float aw = e / s[1];
    g_aw[tid] = aw;
    out_aw[tid] = aw;
}

// ---------------------------------------------------------------------------
// K3: ctx[col] += sum over a 64-row slab of aw[l]*enc[l,col]
// grid (8 col-tiles, 8 row-tiles); deterministic: each (col,rowtile) pair adds
// once via atomicAdd, but to keep bitwise determinism across replays the adds
// are to distinct per-rowtile partials? -> atomicAdd ordering only affects
// rounding ~1e-8; instead keep it deterministic: one block per col tile,
// full 512-row loop, deep unroll.
__global__ void k_context(const float* __restrict__ enc) {
    __shared__ float s_aw[L];
    for (int i = threadIdx.x; i < L; i += blockDim.x) s_aw[i] = g_aw[i];
    __syncthreads();
    int col = blockIdx.x * blockDim.x + threadIdx.x;
    float a0 = 0.f, a1 = 0.f, a2 = 0.f, a3 = 0.f;
#pragma unroll 4
    for (int l = 0; l < L; l += 4) {
        a0 += s_aw[l + 0] * __ldg(&enc[(size_t)(l + 0) * H + col]);
        a1 += s_aw[l + 1] * __ldg(&enc[(size_t)(l + 1) * H + col]);
        a2 += s_aw[l + 2] * __ldg(&enc[(size_t)(l + 2) * H + col]);
        a3 += s_aw[l + 3] * __ldg(&enc[(size_t)(l + 3) * H + col]);
    }
    g_ctx[col] = (a0 + a1) + (a2 + a3);
}

// ---------------------------------------------------------------------------
// K4: x[i] = relu(comb_W[i,:] . cat(emb, ctx) + comb_b[i]); warp-per-row.
__global__ void k_combine(const int* __restrict__ token,
                          const float* __restrict__ embedding,
                          const float* __restrict__ comb_W,
                          const float* __restrict__ comb_b) {
    int warp = (blockIdx.x * blockDim.x + threadIdx.x) >> 5;
    int lane = threadIdx.x & 31;
    if (warp >= H) return;
    const float4* w4   = (const float4*)(comb_W + (size_t)warp * 2 * H);
    const float4* emb4 = (const float4*)(embedding + (size_t)__ldg(token) * H);
    const float4* ctx4 = (const float4*)g_ctx;
    float acc[4] = {0.f, 0.f, 0.f, 0.f};
#pragma unroll
    for (int j = 0; j < 16; j++) {
        int i = lane + 32 * j;
        float4 w = w4[i];
        float4 x = __ldg(&emb4[i]);
        acc[j & 3] += w.x * x.x + w.y * x.y + w.z * x.z + w.w * x.w;
    }
#pragma unroll
    for (int j = 0; j < 16; j++) {
        int i = lane + 32 * j;
        float4 w = w4[i + 512];
        float4 x = __ldg(&ctx4[i]);
        acc[j & 3] += w.x * x.x + w.y * x.y + w.z * x.z + w.w * x.w;
    }
    float a = warpSum(acc[0] + acc[1] + acc[2] + acc[3]);
    if (lane == 0) g_x[warp] = fmaxf(a + __ldg(&comb_b[warp]), 0.f);
}

// ---------------------------------------------------------------------------
// K5: gi = w_ih @ x + b_ih ; gh = w_hh @ h + b_hh ; warp-per-row (12288 rows).
__global__ void k_gates(const float* __restrict__ w_ih,
                        const float* __restrict__ w_hh,
                        const float* __restrict__ b_ih,
                        const float* __restrict__ b_hh,
                        const float* __restrict__ hidden) {
    int warp = (blockIdx.x * blockDim.x + threadIdx.x) >> 5;
    int lane = threadIdx.x & 31;
    if (warp >= 6 * H) return;
    const float4* w4;
    const float4* v4;
    float bias;
    if (warp < 3 * H) {
        w4 = (const float4*)(w_ih + (size_t)warp * H);
        v4 = (const float4*)g_x;
        bias = __ldg(&b_ih[warp]);
    } else {
        int r = warp - 3 * H;
        w4 = (const float4*)(w_hh + (size_t)r * H);
        v4 = (const float4*)hidden;
        bias = __ldg(&b_hh[r]);
    }
    float acc[4] = {0.f, 0.f, 0.f, 0.f};
#pragma unroll
    for (int j = 0; j < 16; j++) {
        int i = lane + 32 * j;
        float4 w = w4[i];
        float4 x = __ldg(&v4[i]);
        acc[j & 3] += w.x * x.x + w.y * x.y + w.z * x.z + w.w * x.w;
    }
    float a = warpSum(acc[0] + acc[1] + acc[2] + acc[3]);
    if (lane == 0) g_gates[warp] = a + bias;
}

// ---------------------------------------------------------------------------
// K6: GRU gate combine -> h_new
__global__ void k_hnew(const float* __restrict__ hidden, float* __restrict__ out_h) {
    int i = blockIdx.x * blockDim.x + threadIdx.x;
    if (i >= H) return;
    const float* gi = g_gates;
    const float* gh = g_gates + 3 * H;
    float r = 1.f / (1.f + expf(-(gi[i] + gh[i])));
    float z = 1.f / (1.f + expf(-(gi[H + i] + gh[H + i])));
    float n = tanhf(gi[2 * H + i] + r * gh[2 * H + i]);
    float hn = (1.f - z) * n + z * hidden[i];
    g_hnew[i] = hn;
    out_h[i] = hn;
}

// ---------------------------------------------------------------------------
// K7: raw logits[v] = out_W[v,:] . h_new + out_b[v]; warp-per-row, 50257 rows.
__global__ void k_logits(const float* __restrict__ out_W,
                         const float* __restrict__ out_b,
                         float* __restrict__ out) {
    int warp = (blockIdx.x * blockDim.x + threadIdx.x) >> 5;
    int lane = threadIdx.x & 31;
    if (warp >= V) return;
    const float4* w4 = (const float4*)(out_W + (size_t)warp * H);
    const float4* v4 = (const float4*)g_hnew;
    float acc[4] = {0.f, 0.f, 0.f, 0.f};
#pragma unroll
    for (int j = 0; j < 16; j++) {
        int i = lane + 32 * j;
        float4 w = w4[i];
        float4 x = __ldg(&v4[i]);
        acc[j & 3] += w.x * x.x + w.y * x.y + w.z * x.z + w.w * x.w;
    }
    float a = warpSum(acc[0] + acc[1] + acc[2] + acc[3]);
    if (lane == 0) out[warp] = a + __ldg(&out_b[warp]);
}

// ---------------------------------------------------------------------------
// K8: logsumexp over raw logits (single block, 1024 threads)
__global__ void k_lse(const float* __restrict__ out) {
    __shared__ float s[32];
    int tid = threadIdx.x, lane = tid & 31, w = tid >> 5;
    float m = -1e30f;
    for (int i = tid; i < V; i += 1024) m = fmaxf(m, __ldg(&out[i]));
#pragma unroll
    for (int o = 16; o; o >>= 1) m = fmaxf(m, __shfl_down_sync(0xffffffffu, m, o));
    if (lane == 0) s[w] = m;
    __syncthreads();
    if (w == 0) {
        m = s[lane];
#pragma unroll
        for (int o = 16; o; o >>= 1) m = fmaxf(m, __shfl_down_sync(0xffffffffu, m, o));
        if (lane == 0) s[0] = m;
    }
    __syncthreads();
    m = s[0];
    float sum = 0.f;
    for (int i = tid; i < V; i += 1024) sum += expf(__ldg(&out[i]) - m);
    sum = warpSum(sum);
    __syncthreads();
    if (lane == 0) s[w] = sum;
    __syncthreads();
    if (w == 0) {
        sum = s[lane];
        sum = warpSum(sum);
        if (lane == 0) g_lse[0] = m + logf(sum);
    }
}

// K9: out[v] -= lse
__global__ void k_logsoftmax(float* __restrict__ out) {
    int i = blockIdx.x * blockDim.x + threadIdx.x;
    if (i < V) out[i] -= g_lse[0];
}

extern "C" void kernel_launch(void* const* d_in, const int* in_sizes, int n_in,
                              void* d_out, int out_size) {
    const int*   token     = (const int*)d_in[0];
    const float* hidden    = (const float*)d_in[1];
    const float* enc       = (const float*)d_in[2];
    const float* embedding = (const float*)d_in[3];
    const float* attn_W    = (const float*)d_in[4];
    const float* attn_b    = (const float*)d_in[5];
    const float* comb_W    = (const float*)d_in[6];
    const float* comb_b    = (const float*)d_in[7];
    const float* w_ih      = (const float*)d_in[8];
    const float* w_hh      = (const float*)d_in[9];
    const float* b_ih      = (const float*)d_in[10];
    const float* b_hh      = (const float*)d_in[11];
    const float* out_W     = (const float*)d_in[12];
    const float* out_b     = (const float*)d_in[13];

    float* out = (float*)d_out;
    float* out_logits = out;
    float* out_h      = out + V;
    float* out_aw     = out + V + H;

    // warp-per-row GEMVs: 8 rows per 256-thread block
    k_attn_scores<<<(L + 7) / 8, 256>>>(token, hidden, embedding, attn_W, attn_b);
    k_softmax<<<1, L>>>(out_aw);
    k_context<<<H / 256, 256>>>(enc);
    k_combine<<<(H + 7) / 8, 256>>>(token, embedding, comb_W, comb_b);
    k_gates<<<(6 * H + 7) / 8, 256>>>(w_ih, w_hh, b_ih, b_hh, hidden);
    k_hnew<<<H / 256, 256>>>(hidden, out_h);
    k_logits<<<(V + 7) / 8, 256>>>(out_W, out_b, out_logits);
    k_lse<<<1, 1024>>>(out_logits);
    k_logsoftmax<<<(V + 255) / 256, 256>>>(out_logits);
}

// round 3
// speedup vs baseline: 1.5537x; 1.1736x over previous
#include <cuda_runtime.h>
#include <math.h>

// ---------------- scratch (device globals; no allocation allowed) ----------
__device__ float g_scores[512];         // attn logits
__device__ float g_aw[512];             // attn softmax weights
__device__ float g_ctx_part[8 * 2048];  // split-K context partials
__device__ float g_x[2048];             // relu(attn_combine)
__device__ float g_gates[12288];        // gi[0:6144), gh[6144:12288)
__device__ float g_hnew[2048];          // new hidden
__device__ float g_lse[1];              // logsumexp of raw logits

#define H 2048
#define V 50257
#define L 512

__device__ __forceinline__ float warpSum(float v) {
#pragma unroll
    for (int o = 16; o; o >>= 1) v += __shfl_down_sync(0xffffffffu, v, o);
    return v;
}

// Dot of one 512-float4 (2048 float) weight segment against an smem vector
// segment. Front-batches all 16 LDG.128 (MLP_p1 = 16), then FMAs vs LDS.128.
__device__ __forceinline__ float warpDot512(const float4* __restrict__ w4,
                                            const float4* __restrict__ sv,
                                            int lane) {
    float4 wr[16];
#pragma unroll
    for (int j = 0; j < 16; j++) wr[j] = w4[lane + 32 * j];
    float a0 = 0.f, a1 = 0.f, a2 = 0.f, a3 = 0.f;
#pragma unroll
    for (int j = 0; j < 16; j++) {
        float4 v = sv[lane + 32 * j];
        a0 += wr[j].x * v.x;
        a1 += wr[j].y * v.y;
        a2 += wr[j].z * v.z;
        a3 += wr[j].w * v.w;
    }
    return warpSum((a0 + a1) + (a2 + a3));
}

// ---------------------------------------------------------------------------
// K1: attn scores. 2 warps per row; 4 rows per 256-thread block; 128 blocks.
// smem: cat(emb, hidden) staged once (1024 float4 = 16KB).
__global__ void __launch_bounds__(256, 3)
k_attn_scores(const int* __restrict__ token, const float* __restrict__ hidden,
              const float* __restrict__ embedding,
              const float* __restrict__ attn_W, const float* __restrict__ attn_b) {
    __shared__ float4 sv[1024];
    __shared__ float sred[8];
    int tid = threadIdx.x, lane = tid & 31, warp = tid >> 5;
    const float4* emb4 = (const float4*)(embedding + (size_t)__ldg(token) * H);
    const float4* hid4 = (const float4*)hidden;
#pragma unroll
    for (int k = 0; k < 2; k++) {
        int i = tid + 256 * k;
        sv[i] = __ldg(&emb4[i]);
        sv[i + 512] = __ldg(&hid4[i]);
    }
    __syncthreads();
    int row = blockIdx.x * 4 + (warp >> 1);
    int half = warp & 1;
    const float4* w4 = (const float4*)(attn_W + (size_t)row * 2 * H) + half * 512;
    float p = warpDot512(w4, sv + half * 512, lane);
    if (lane == 0) sred[warp] = p;
    __syncthreads();
    if (tid < 4) {
        int r = blockIdx.x * 4 + tid;
        g_scores[r] = sred[2 * tid] + sred[2 * tid + 1] + __ldg(&attn_b[r]);
    }
}

// ---------------------------------------------------------------------------
// K2: softmax over 512 scores (1 block, 512 threads).
__global__ void k_softmax(float* __restrict__ out_aw) {
    __shared__ float s[32];
    int tid = threadIdx.x, lane = tid & 31, w = tid >> 5;
    float v = g_scores[tid];
    float m = v;
#pragma unroll
    for (int o = 16; o; o >>= 1) m = fmaxf(m, __shfl_down_sync(0xffffffffu, m, o));
    if (lane == 0) s[w] = m;
    __syncthreads();
    if (w == 0) {
        m = (lane < 16) ? s[lane] : -1e30f;
#pragma unroll
        for (int o = 16; o; o >>= 1) m = fmaxf(m, __shfl_down_sync(0xffffffffu, m, o));
        if (lane == 0) s[0] = m;
    }
    __syncthreads();
    m = s[0];
    __syncthreads();
    float e = expf(v - m);
    float sum = warpSum(e);
    if (lane == 0) s[w] = sum;
    __syncthreads();
    if (w == 0) {
        sum = (lane < 16) ? s[lane] : 0.f;
        sum = warpSum(sum);
        if (lane == 0) s[1] = sum;
    }
    __syncthreads();
    float aw = e / s[1];
    g_aw[tid] = aw;
    out_aw[tid] = aw;
}

// ---------------------------------------------------------------------------
// K3: split-K context partials. grid (8 col-tiles, 8 row-tiles) = 64 blocks.
// Block (x,y): cols [256x, 256x+256), rows [64y, 64y+64).
__global__ void k_context_part(const float* __restrict__ enc) {
    __shared__ float s_aw[64];
    int tid = threadIdx.x;
    int r0 = blockIdx.y * 64;
    if (tid < 64) s_aw[tid] = g_aw[r0 + tid];
    __syncthreads();
    int col = blockIdx.x * 256 + tid;
    float a0 = 0.f, a1 = 0.f, a2 = 0.f, a3 = 0.f;
#pragma unroll 4
    for (int l = 0; l < 64; l += 4) {
        a0 += s_aw[l + 0] * __ldg(&enc[(size_t)(r0 + l + 0) * H + col]);
        a1 += s_aw[l + 1] * __ldg(&enc[(size_t)(r0 + l + 1) * H + col]);
        a2 += s_aw[l + 2] * __ldg(&enc[(size_t)(r0 + l + 2) * H + col]);
        a3 += s_aw[l + 3] * __ldg(&enc[(size_t)(r0 + l + 3) * H + col]);
    }
    g_ctx_part[blockIdx.y * H + col] = (a0 + a1) + (a2 + a3);
}

// ---------------------------------------------------------------------------
// K4: combine. 2 warps/row, 4 rows/block, 512 blocks.
// Staging also performs the context partial reduction (fixed order).
__global__ void __launch_bounds__(256, 3)
k_combine(const int* __restrict__ token, const float* __restrict__ embedding,
          const float* __restrict__ comb_W, const float* __restrict__ comb_b) {
    __shared__ float4 sv[1024];
    __shared__ float sred[8];
    int tid = threadIdx.x, lane = tid & 31, warp = tid >> 5;
    const float4* emb4 = (const float4*)(embedding + (size_t)__ldg(token) * H);
    const float4* part4 = (const float4*)g_ctx_part;
#pragma unroll
    for (int k = 0; k < 2; k++) {
        int i = tid + 256 * k;
        sv[i] = __ldg(&emb4[i]);
        float4 c = part4[i];
#pragma unroll
        for (int p = 1; p < 8; p++) {
            float4 q = part4[p * 512 + i];
            c.x += q.x; c.y += q.y; c.z += q.z; c.w += q.w;
        }
        sv[i + 512] = c;
    }
    __syncthreads();
    int row = blockIdx.x * 4 + (warp >> 1);
    int half = warp & 1;
    const float4* w4 = (const float4*)(comb_W + (size_t)row * 2 * H) + half * 512;
    float p = warpDot512(w4, sv + half * 512, lane);
    if (lane == 0) sred[warp] = p;
    __syncthreads();
    if (tid < 4) {
        int r = blockIdx.x * 4 + tid;
        g_x[r] = fmaxf(sred[2 * tid] + sred[2 * tid + 1] + __ldg(&comb_b[r]), 0.f);
    }
}

// ---------------------------------------------------------------------------
// K5: GRU gates. 1 warp/row, 8 rows/block, 1536 blocks.
// Blocks [0,768): rows 0..6143 use g_x/w_ih; blocks [768,1536): hidden/w_hh.
__global__ void __launch_bounds__(256, 3)
k_gates(const float* __restrict__ w_ih, const float* __restrict__ w_hh,
        const float* __restrict__ b_ih, const float* __restrict__ b_hh,
        const float* __restrict__ hidden) {
    __shared__ float4 sv[512];
    int tid = threadIdx.x, lane = tid & 31, warp = tid >> 5;
    bool ih = blockIdx.x < 768;
    const float4* v4 = ih ? (const float4*)g_x : (const float4*)hidden;
#pragma unroll
    for (int k = 0; k < 2; k++) sv[tid + 256 * k] = __ldg(&v4[tid + 256 * k]);
    __syncthreads();
    int row = blockIdx.x * 8 + warp;             // global row in [0, 12288)
    int lrow = ih ? row : row - 3 * H;           // row within its matrix
    const float* W = ih ? w_ih : w_hh;
    const float4* w4 = (const float4*)(W + (size_t)lrow * H);
    float a = warpDot512(w4, sv, lane);
    if (lane == 0)
        g_gates[row] = a + __ldg(ih ? &b_ih[lrow] : &b_hh[lrow]);
}

// ---------------------------------------------------------------------------
// K6: GRU gate combine -> h_new
__global__ void k_hnew(const float* __restrict__ hidden, float* __restrict__ out_h) {
    int i = blockIdx.x * blockDim.x + threadIdx.x;
    if (i >= H) return;
    const float* gi = g_gates;
    const float* gh = g_gates + 3 * H;
    float r = 1.f / (1.f + expf(-(gi[i] + gh[i])));
    float z = 1.f / (1.f + expf(-(gi[H + i] + gh[H + i])));
    float n = tanhf(gi[2 * H + i] + r * gh[2 * H + i]);
    float hn = (1.f - z) * n + z * hidden[i];
    g_hnew[i] = hn;
    out_h[i] = hn;
}

// ---------------------------------------------------------------------------
// K7: logits GEMV (412 MB). 1 warp/row, 8 rows/block, 6283 blocks.
__global__ void __launch_bounds__(256, 3)
k_logits(const float* __restrict__ out_W, const float* __restrict__ out_b,
         float* __restrict__ out) {
    __shared__ float4 sv[512];
    int tid = threadIdx.x, lane = tid & 31, warp = tid >> 5;
    const float4* v4 = (const float4*)g_hnew;
#pragma unroll
    for (int k = 0; k < 2; k++) sv[tid + 256 * k] = __ldg(&v4[tid + 256 * k]);
    __syncthreads();
    int row = blockIdx.x * 8 + warp;
    if (row >= V) return;
    const float4* w4 = (const float4*)(out_W + (size_t)row * H);
    float a = warpDot512(w4, sv, lane);
    if (lane == 0) out[row] = a + __ldg(&out_b[row]);
}

// ---------------------------------------------------------------------------
// K8: logsumexp over raw logits (single block, 1024 threads)
__global__ void k_lse(const float* __restrict__ out) {
    __shared__ float s[32];
    int tid = threadIdx.x, lane = tid & 31, w = tid >> 5;
    float m = -1e30f;
    for (int i = tid; i < V; i += 1024) m = fmaxf(m, __ldg(&out[i]));
#pragma unroll
    for (int o = 16; o; o >>= 1) m = fmaxf(m, __shfl_down_sync(0xffffffffu, m, o));
    if (lane == 0) s[w] = m;
    __syncthreads();
    if (w == 0) {
        m = s[lane];
#pragma unroll
        for (int o = 16; o; o >>= 1) m = fmaxf(m, __shfl_down_sync(0xffffffffu, m, o));
        if (lane == 0) s[0] = m;
    }
    __syncthreads();
    m = s[0];
    float sum = 0.f;
    for (int i = tid; i < V; i += 1024) sum += expf(__ldg(&out[i]) - m);
    sum = warpSum(sum);
    __syncthreads();
    if (lane == 0) s[w] = sum;
    __syncthreads();
    if (w == 0) {
        sum = s[lane];
        sum = warpSum(sum);
        if (lane == 0) g_lse[0] = m + logf(sum);
    }
}

// K9: out[v] -= lse
__global__ void k_logsoftmax(float* __restrict__ out) {
    int i = blockIdx.x * blockDim.x + threadIdx.x;
    if (i < V) out[i] -= g_lse[0];
}

extern "C" void kernel_launch(void* const* d_in, const int* in_sizes, int n_in,
                              void* d_out, int out_size) {
    const int*   token     = (const int*)d_in[0];
    const float* hidden    = (const float*)d_in[1];
    const float* enc       = (const float*)d_in[2];
    const float* embedding = (const float*)d_in[3];
    const float* attn_W    = (const float*)d_in[4];
    const float* attn_b    = (const float*)d_in[5];
    const float* comb_W    = (const float*)d_in[6];
    const float* comb_b    = (const float*)d_in[7];
    const float* w_ih      = (const float*)d_in[8];
    const float* w_hh      = (const float*)d_in[9];
    const float* b_ih      = (const float*)d_in[10];
    const float* b_hh      = (const float*)d_in[11];
    const float* out_W     = (const float*)d_in[12];
    const float* out_b     = (const float*)d_in[13];

    float* out = (float*)d_out;
    float* out_logits = out;
    float* out_h      = out + V;
    float* out_aw     = out + V + H;

    k_attn_scores<<<L / 4, 256>>>(token, hidden, embedding, attn_W, attn_b);
    k_softmax<<<1, L>>>(out_aw);
    k_context_part<<<dim3(8, 8), 256>>>(enc);
    k_combine<<<H / 4, 256>>>(token, embedding, comb_W, comb_b);
    k_gates<<<6 * H / 8, 256>>>(w_ih, w_hh, b_ih, b_hh, hidden);
    k_hnew<<<H / 256, 256>>>(hidden, out_h);
    k_logits<<<(V + 7) / 8, 256>>>(out_W, out_b, out_logits);
    k_lse<<<1, 1024>>>(out_logits);
    k_logsoftmax<<<(V + 255) / 256, 256>>>(out_logits);
}

// round 4
// speedup vs baseline: 1.6953x; 1.0911x over previous
#include <cuda_runtime.h>
#include <math.h>

// ---------------- scratch (device globals; no allocation allowed) ----------
__device__ float g_scores[512];         // attn logits
__device__ float g_aw[512];             // attn softmax weights
__device__ float g_ctx_part[8 * 2048];  // split-K context partials
__device__ float g_ctx[2048];           // reduced context
__device__ float g_x[2048];             // relu(attn_combine)
__device__ float g_gates[12288];        // gi[0:6144), gh[6144:12288)
__device__ float g_hnew[2048];          // new hidden
__device__ float g_lse[1];              // logsumexp of raw logits

#define H 2048
#define V 50257
#define L 512

__device__ __forceinline__ float warpSum(float v) {
#pragma unroll
    for (int o = 16; o; o >>= 1) v += __shfl_down_sync(0xffffffffu, v, o);
    return v;
}

// Dot of one 512-float4 (2048 float) weight segment vs smem vector segment.
// Front-batches all 16 LDG.128 with streaming (evict-first) hint.
__device__ __forceinline__ float warpDot512(const float4* __restrict__ w4,
                                            const float4* __restrict__ sv,
                                            int lane) {
    float4 wr[16];
#pragma unroll
    for (int j = 0; j < 16; j++) wr[j] = __ldcs(&w4[lane + 32 * j]);
    float a0 = 0.f, a1 = 0.f, a2 = 0.f, a3 = 0.f;
#pragma unroll
    for (int j = 0; j < 16; j++) {
        float4 v = sv[lane + 32 * j];
        a0 += wr[j].x * v.x;
        a1 += wr[j].y * v.y;
        a2 += wr[j].z * v.z;
        a3 += wr[j].w * v.w;
    }
    return warpSum((a0 + a1) + (a2 + a3));
}

// ---------------------------------------------------------------------------
// K1: attn scores. 2 warps per row; 4 rows per 256-thread block; 128 blocks.
__global__ void __launch_bounds__(256, 3)
k_attn_scores(const int* __restrict__ token, const float* __restrict__ hidden,
              const float* __restrict__ embedding,
              const float* __restrict__ attn_W, const float* __restrict__ attn_b) {
    __shared__ float4 sv[1024];
    __shared__ float sred[8];
    int tid = threadIdx.x, lane = tid & 31, warp = tid >> 5;
    const float4* emb4 = (const float4*)(embedding + (size_t)__ldg(token) * H);
    const float4* hid4 = (const float4*)hidden;
#pragma unroll
    for (int k = 0; k < 2; k++) {
        int i = tid + 256 * k;
        sv[i] = __ldg(&emb4[i]);
        sv[i + 512] = __ldg(&hid4[i]);
    }
    __syncthreads();
    int row = blockIdx.x * 4 + (warp >> 1);
    int half = warp & 1;
    const float4* w4 = (const float4*)(attn_W + (size_t)row * 2 * H) + half * 512;
    float p = warpDot512(w4, sv + half * 512, lane);
    if (lane == 0) sred[warp] = p;
    __syncthreads();
    if (tid < 4) {
        int r = blockIdx.x * 4 + tid;
        g_scores[r] = sred[2 * tid] + sred[2 * tid + 1] + __ldg(&attn_b[r]);
    }
}

// ---------------------------------------------------------------------------
// K2: softmax over 512 scores (1 block, 512 threads).
__global__ void k_softmax(float* __restrict__ out_aw) {
    __shared__ float s[32];
    int tid = threadIdx.x, lane = tid & 31, w = tid >> 5;
    float v = g_scores[tid];
    float m = v;
#pragma unroll
    for (int o = 16; o; o >>= 1) m = fmaxf(m, __shfl_down_sync(0xffffffffu, m, o));
    if (lane == 0) s[w] = m;
    __syncthreads();
    if (w == 0) {
        m = (lane < 16) ? s[lane] : -1e30f;
#pragma unroll
        for (int o = 16; o; o >>= 1) m = fmaxf(m, __shfl_down_sync(0xffffffffu, m, o));
        if (lane == 0) s[0] = m;
    }
    __syncthreads();
    m = s[0];
    __syncthreads();
    float e = expf(v - m);
    float sum = warpSum(e);
    if (lane == 0) s[w] = sum;
    __syncthreads();
    if (w == 0) {
        sum = (lane < 16) ? s[lane] : 0.f;
        sum = warpSum(sum);
        if (lane == 0) s[1] = sum;
    }
    __syncthreads();
    float aw = e / s[1];
    g_aw[tid] = aw;
    out_aw[tid] = aw;
}

// ---------------------------------------------------------------------------
// K3: split-K context partials. grid (8 col-tiles, 8 row-tiles) = 64 blocks.
__global__ void k_context_part(const float* __restrict__ enc) {
    __shared__ float s_aw[64];
    int tid = threadIdx.x;
    int r0 = blockIdx.y * 64;
    if (tid < 64) s_aw[tid] = g_aw[r0 + tid];
    __syncthreads();
    int col = blockIdx.x * 256 + tid;
    float a0 = 0.f, a1 = 0.f, a2 = 0.f, a3 = 0.f;
#pragma unroll 4
    for (int l = 0; l < 64; l += 4) {
        a0 += s_aw[l + 0] * __ldcs(&enc[(size_t)(r0 + l + 0) * H + col]);
        a1 += s_aw[l + 1] * __ldcs(&enc[(size_t)(r0 + l + 1) * H + col]);
        a2 += s_aw[l + 2] * __ldcs(&enc[(size_t)(r0 + l + 2) * H + col]);
        a3 += s_aw[l + 3] * __ldcs(&enc[(size_t)(r0 + l + 3) * H + col]);
    }
    g_ctx_part[blockIdx.y * H + col] = (a0 + a1) + (a2 + a3);
}

// K3b: reduce 8 partials -> g_ctx (8 blocks x 256 threads).
__global__ void k_ctx_reduce() {
    int i = blockIdx.x * blockDim.x + threadIdx.x;  // 0..2047
    float c = g_ctx_part[i];
#pragma unroll
    for (int p = 1; p < 8; p++) c += g_ctx_part[p * H + i];
    g_ctx[i] = c;
}

// ---------------------------------------------------------------------------
// K4: combine. 2 warps/row, 4 rows/block, 512 blocks. Stages cat(emb, ctx).
__global__ void __launch_bounds__(256, 3)
k_combine(const int* __restrict__ token, const float* __restrict__ embedding,
          const float* __restrict__ comb_W, const float* __restrict__ comb_b) {
    __shared__ float4 sv[1024];
    __shared__ float sred[8];
    int tid = threadIdx.x, lane = tid & 31, warp = tid >> 5;
    const float4* emb4 = (const float4*)(embedding + (size_t)__ldg(token) * H);
    const float4* ctx4 = (const float4*)g_ctx;
#pragma unroll
    for (int k = 0; k < 2; k++) {
        int i = tid + 256 * k;
        sv[i] = __ldg(&emb4[i]);
        sv[i + 512] = __ldg(&ctx4[i]);
    }
    __syncthreads();
    int row = blockIdx.x * 4 + (warp >> 1);
    int half = warp & 1;
    const float4* w4 = (const float4*)(comb_W + (size_t)row * 2 * H) + half * 512;
    float p = warpDot512(w4, sv + half * 512, lane);
    if (lane == 0) sred[warp] = p;
    __syncthreads();
    if (tid < 4) {
        int r = blockIdx.x * 4 + tid;
        g_x[r] = fmaxf(sred[2 * tid] + sred[2 * tid + 1] + __ldg(&comb_b[r]), 0.f);
    }
}

// ---------------------------------------------------------------------------
// K5: GRU gates. 1 warp/row, 8 rows/block, 1536 blocks.
__global__ void __launch_bounds__(256, 3)
k_gates(const float* __restrict__ w_ih, const float* __restrict__ w_hh,
        const float* __restrict__ b_ih, const float* __restrict__ b_hh,
        const float* __restrict__ hidden) {
    __shared__ float4 sv[512];
    int tid = threadIdx.x, lane = tid & 31, warp = tid >> 5;
    bool ih = blockIdx.x < 768;
    const float4* v4 = ih ? (const float4*)g_x : (const float4*)hidden;
#pragma unroll
    for (int k = 0; k < 2; k++) sv[tid + 256 * k] = __ldg(&v4[tid + 256 * k]);
    __syncthreads();
    int row = blockIdx.x * 8 + warp;
    int lrow = ih ? row : row - 3 * H;
    const float* W = ih ? w_ih : w_hh;
    const float4* w4 = (const float4*)(W + (size_t)lrow * H);
    float a = warpDot512(w4, sv, lane);
    if (lane == 0)
        g_gates[row] = a + __ldg(ih ? &b_ih[lrow] : &b_hh[lrow]);
}

// ---------------------------------------------------------------------------
// K6: GRU gate combine -> h_new
__global__ void k_hnew(const float* __restrict__ hidden, float* __restrict__ out_h) {
    int i = blockIdx.x * blockDim.x + threadIdx.x;
    if (i >= H) return;
    const float* gi = g_gates;
    const float* gh = g_gates + 3 * H;
    float r = 1.f / (1.f + expf(-(gi[i] + gh[i])));
    float z = 1.f / (1.f + expf(-(gi[H + i] + gh[H + i])));
    float n = tanhf(gi[2 * H + i] + r * gh[2 * H + i]);
    float hn = (1.f - z) * n + z * hidden[i];
    g_hnew[i] = hn;
    out_h[i] = hn;
}

// ---------------------------------------------------------------------------
// K7: logits GEMV (412 MB). 1 warp/row, 8 rows/block, 6283 blocks.
__global__ void __launch_bounds__(256, 3)
k_logits(const float* __restrict__ out_W, const float* __restrict__ out_b,
         float* __restrict__ out) {
    __shared__ float4 sv[512];
    int tid = threadIdx.x, lane = tid & 31, warp = tid >> 5;
    const float4* v4 = (const float4*)g_hnew;
#pragma unroll
    for (int k = 0; k < 2; k++) sv[tid + 256 * k] = __ldg(&v4[tid + 256 * k]);
    __syncthreads();
    int row = blockIdx.x * 8 + warp;
    if (row >= V) return;
    const float4* w4 = (const float4*)(out_W + (size_t)row * H);
    float a = warpDot512(w4, sv, lane);
    if (lane == 0) out[row] = a + __ldg(&out_b[row]);
}

// ---------------------------------------------------------------------------
// K8: logsumexp over raw logits (single block, 1024 threads)
__global__ void k_lse(const float* __restrict__ out) {
    __shared__ float s[32];
    int tid = threadIdx.x, lane = tid & 31, w = tid >> 5;
    float m = -1e30f;
    for (int i = tid; i < V; i += 1024) m = fmaxf(m, __ldg(&out[i]));
#pragma unroll
    for (int o = 16; o; o >>= 1) m = fmaxf(m, __shfl_down_sync(0xffffffffu, m, o));
    if (lane == 0) s[w] = m;
    __syncthreads();
    if (w == 0) {
        m = s[lane];
#pragma unroll
        for (int o = 16; o; o >>= 1) m = fmaxf(m, __shfl_down_sync(0xffffffffu, m, o));
        if (lane == 0) s[0] = m;
    }
    __syncthreads();
    m = s[0];
    float sum = 0.f;
    for (int i = tid; i < V; i += 1024) sum += expf(__ldg(&out[i]) - m);
    sum = warpSum(sum);
    __syncthreads();
    if (lane == 0) s[w] = sum;
    __syncthreads();
    if (w == 0) {
        sum = s[lane];
        sum = warpSum(sum);
        if (lane == 0) g_lse[0] = m + logf(sum);
    }
}

// K9: out[v] -= lse
__global__ void k_logsoftmax(float* __restrict__ out) {
    int i = blockIdx.x * blockDim.x + threadIdx.x;
    if (i < V) out[i] -= g_lse[0];
}

extern "C" void kernel_launch(void* const* d_in, const int* in_sizes, int n_in,
                              void* d_out, int out_size) {
    const int*   token     = (const int*)d_in[0];
    const float* hidden    = (const float*)d_in[1];
    const float* enc       = (const float*)d_in[2];
    const float* embedding = (const float*)d_in[3];
    const float* attn_W    = (const float*)d_in[4];
    const float* attn_b    = (const float*)d_in[5];
    const float* comb_W    = (const float*)d_in[6];
    const float* comb_b    = (const float*)d_in[7];
    const float* w_ih      = (const float*)d_in[8];
    const float* w_hh      = (const float*)d_in[9];
    const float* b_ih      = (const float*)d_in[10];
    const float* b_hh      = (const float*)d_in[11];
    const float* out_W     = (const float*)d_in[12];
    const float* out_b     = (const float*)d_in[13];

    float* out = (float*)d_out;
    float* out_logits = out;
    float* out_h      = out + V;
    float* out_aw     = out + V + H;

    k_attn_scores<<<L / 4, 256>>>(token, hidden, embedding, attn_W, attn_b);
    k_softmax<<<1, L>>>(out_aw);
    k_context_part<<<dim3(8, 8), 256>>>(enc);
    k_ctx_reduce<<<H / 256, 256>>>();
    k_combine<<<H / 4, 256>>>(token, embedding, comb_W, comb_b);
    k_gates<<<6 * H / 8, 256>>>(w_ih, w_hh, b_ih, b_hh, hidden);
    k_hnew<<<H / 256, 256>>>(hidden, out_h);
    k_logits<<<(V + 7) / 8, 256>>>(out_W, out_b, out_logits);
    k_lse<<<1, 1024>>>(out_logits);
    k_logsoftmax<<<(V + 255) / 256, 256>>>(out_logits);
}